// round 2
// baseline (speedup 1.0000x reference)
#include <cuda_runtime.h>

#define N_NODES 100000
#define N_EDGES 1600000

// Scratch (no allocation allowed -> __device__ globals)
__device__ float g_deg[N_NODES];
__device__ float g_dis[N_NODES];
__device__ float g_agg[2 * N_NODES];   // layer-1 2-float aggregate per node
__device__ float g_s[N_NODES];         // per-node scalar after layer-1 + W2

// ---------------------------------------------------------------------------
// K0: zero deg, agg, out
__global__ void k_zero(float* __restrict__ out) {
    int i = blockIdx.x * blockDim.x + threadIdx.x;
    if (i < N_NODES) {
        g_deg[i] = 0.0f;
        g_agg[2 * i] = 0.0f;
        g_agg[2 * i + 1] = 0.0f;
        out[i] = 0.0f;
    }
}

// K1: degree of target nodes (edge_index is int32 — JAX x64 disabled)
__global__ void k_deg(const int* __restrict__ col) {
    int e = blockIdx.x * blockDim.x + threadIdx.x;
    if (e < N_EDGES) {
        atomicAdd(&g_deg[col[e]], 1.0f);
    }
}

// K2: deg^-1/2 (0 where deg==0)
__global__ void k_dis() {
    int n = blockIdx.x * blockDim.x + threadIdx.x;
    if (n < N_NODES) {
        float d = g_deg[n];
        g_dis[n] = (d > 0.0f) ? rsqrtf(d) : 0.0f;
    }
}

// K3: layer-1 edge scatter: agg[col] += norm * x[row]  (2 floats)
__global__ void k_edge1(const int* __restrict__ row,
                        const int* __restrict__ col,
                        const float* __restrict__ x) {
    int e = blockIdx.x * blockDim.x + threadIdx.x;
    if (e < N_EDGES) {
        int r = row[e];
        int c = col[e];
        float nm = g_dis[r] * g_dis[c];
        float2 xv = ((const float2*)x)[r];
        atomicAdd(&g_agg[2 * c],     nm * xv.x);
        atomicAdd(&g_agg[2 * c + 1], nm * xv.y);
    }
}

// K4: per-node: s[n] = sum_f relu(a0*W1[0][f] + a1*W1[1][f] + b1[f]) * W2[f]
__global__ void k_nodemid(const float* __restrict__ W1,
                          const float* __restrict__ b1,
                          const float* __restrict__ W2) {
    __shared__ float sW1a[64], sW1b[64], sb1[64], sW2[64];
    int t = threadIdx.x;
    if (t < 64) {
        sW1a[t] = W1[t];        // W1[0][f]
        sW1b[t] = W1[64 + t];   // W1[1][f]
        sb1[t]  = b1[t];
        sW2[t]  = W2[t];
    }
    __syncthreads();
    int n = blockIdx.x * blockDim.x + t;
    if (n < N_NODES) {
        float a0 = g_agg[2 * n];
        float a1 = g_agg[2 * n + 1];
        float s = 0.0f;
#pragma unroll
        for (int f = 0; f < 64; f++) {
            float h = fmaf(a1, sW1b[f], fmaf(a0, sW1a[f], sb1[f]));
            s = fmaf(fmaxf(h, 0.0f), sW2[f], s);
        }
        g_s[n] = s;
    }
}

// K5: layer-2 edge scatter: out[col] += norm * s[row]
__global__ void k_edge2(const int* __restrict__ row,
                        const int* __restrict__ col,
                        float* __restrict__ out) {
    int e = blockIdx.x * blockDim.x + threadIdx.x;
    if (e < N_EDGES) {
        int r = row[e];
        int c = col[e];
        float nm = g_dis[r] * g_dis[c];
        atomicAdd(&out[c], nm * g_s[r]);
    }
}

// K6: out = relu(out + b2)
__global__ void k_final(float* __restrict__ out, const float* __restrict__ b2) {
    int n = blockIdx.x * blockDim.x + threadIdx.x;
    if (n < N_NODES) {
        out[n] = fmaxf(out[n] + b2[0], 0.0f);
    }
}

// ---------------------------------------------------------------------------
extern "C" void kernel_launch(void* const* d_in, const int* in_sizes, int n_in,
                              void* d_out, int out_size) {
    const float* x    = (const float*)d_in[0];   // [N,2] f32
    const int*   ei   = (const int*)d_in[1];     // [2,E] int32 (JAX x64 off)
    const float* W1   = (const float*)d_in[2];   // [2,64]
    const float* b1   = (const float*)d_in[3];   // [64]
    const float* W2   = (const float*)d_in[4];   // [64,1]
    const float* b2   = (const float*)d_in[5];   // [1]
    float*       out  = (float*)d_out;           // [N,1]

    const int* row = ei;            // source
    const int* col = ei + N_EDGES;  // target

    const int BT = 256;
    const int nodeBlocks = (N_NODES + BT - 1) / BT;
    const int edgeBlocks = (N_EDGES + BT - 1) / BT;

    k_zero   <<<nodeBlocks, BT>>>(out);
    k_deg    <<<edgeBlocks, BT>>>(col);
    k_dis    <<<nodeBlocks, BT>>>();
    k_edge1  <<<edgeBlocks, BT>>>(row, col, x);
    k_nodemid<<<nodeBlocks, BT>>>(W1, b1, W2);
    k_edge2  <<<edgeBlocks, BT>>>(row, col, out);
    k_final  <<<nodeBlocks, BT>>>(out, b2);
}

// round 3
// speedup vs baseline: 1.3557x; 1.3557x over previous
#include <cuda_runtime.h>

#define N_NODES 100000
#define N_EDGES 1600000

// Scratch (__device__ globals; no allocation allowed)
__device__ float  g_deg[N_NODES];
__device__ float  g_dis[N_NODES];
__device__ float2 g_y[N_NODES];        // y[n] = dis[n] * x[n]  (outgoing msg, layer 1)
__device__ float2 g_agg[N_NODES];      // raw scatter target, layer 1 (pre dis[c] scale)
__device__ float  g_t[N_NODES];        // t[n] = dis[n] * s[n]  (outgoing msg, layer 2)

// v2 float reduction (one L2 sector instead of two)
__device__ __forceinline__ void red_add_v2(float2* addr, float a, float b) {
    asm volatile("red.global.add.v2.f32 [%0], {%1, %2};"
                 :: "l"(addr), "f"(a), "f"(b) : "memory");
}

// ---------------------------------------------------------------------------
// K0: zero deg, agg, out
__global__ void k_zero(float* __restrict__ out) {
    int i = blockIdx.x * blockDim.x + threadIdx.x;
    if (i < N_NODES) {
        g_deg[i] = 0.0f;
        g_agg[i] = make_float2(0.0f, 0.0f);
        out[i]   = 0.0f;
    }
}

// K1: degree of target nodes (4 edges/thread, int4 stream)
__global__ void k_deg(const int4* __restrict__ col4) {
    int i = blockIdx.x * blockDim.x + threadIdx.x;
    if (i < N_EDGES / 4) {
        int4 c = col4[i];
        atomicAdd(&g_deg[c.x], 1.0f);
        atomicAdd(&g_deg[c.y], 1.0f);
        atomicAdd(&g_deg[c.z], 1.0f);
        atomicAdd(&g_deg[c.w], 1.0f);
    }
}

// K2: dis = deg^-1/2 (0 if deg==0);  y[n] = dis[n]*x[n]
__global__ void k_dis(const float* __restrict__ x) {
    int n = blockIdx.x * blockDim.x + threadIdx.x;
    if (n < N_NODES) {
        float d   = g_deg[n];
        float dis = (d > 0.0f) ? rsqrtf(d) : 0.0f;
        g_dis[n]  = dis;
        float2 xv = ((const float2*)x)[n];
        g_y[n]    = make_float2(dis * xv.x, dis * xv.y);
    }
}

// K3: layer-1 edge scatter: agg_raw[c] += y[r]   (1 gather sector + 1 atomic sector)
__global__ void k_edge1(const int4* __restrict__ row4,
                        const int4* __restrict__ col4) {
    int i = blockIdx.x * blockDim.x + threadIdx.x;
    if (i < N_EDGES / 4) {
        int4 r = row4[i];
        int4 c = col4[i];
        float2 y0 = g_y[r.x];
        float2 y1 = g_y[r.y];
        float2 y2 = g_y[r.z];
        float2 y3 = g_y[r.w];
        red_add_v2(&g_agg[c.x], y0.x, y0.y);
        red_add_v2(&g_agg[c.y], y1.x, y1.y);
        red_add_v2(&g_agg[c.z], y2.x, y2.y);
        red_add_v2(&g_agg[c.w], y3.x, y3.y);
    }
}

// K4: per-node MLP middle:
//   a = dis[n] * agg_raw[n]
//   s = sum_f relu(a0*W1[0][f] + a1*W1[1][f] + b1[f]) * W2[f]
//   t[n] = dis[n] * s
__global__ void k_nodemid(const float* __restrict__ W1,
                          const float* __restrict__ b1,
                          const float* __restrict__ W2) {
    __shared__ float sW1a[64], sW1b[64], sb1[64], sW2[64];
    int t = threadIdx.x;
    if (t < 64) {
        sW1a[t] = W1[t];        // W1[0][f]
        sW1b[t] = W1[64 + t];   // W1[1][f]
        sb1[t]  = b1[t];
        sW2[t]  = W2[t];
    }
    __syncthreads();
    int n = blockIdx.x * blockDim.x + t;
    if (n < N_NODES) {
        float dis = g_dis[n];
        float2 ar = g_agg[n];
        float a0 = dis * ar.x;
        float a1 = dis * ar.y;
        float s = 0.0f;
#pragma unroll
        for (int f = 0; f < 64; f++) {
            float h = fmaf(a1, sW1b[f], fmaf(a0, sW1a[f], sb1[f]));
            s = fmaf(fmaxf(h, 0.0f), sW2[f], s);
        }
        g_t[n] = dis * s;
    }
}

// K5: layer-2 edge scatter: out_raw[c] += t[r]  (1 gather sector + 1 atomic sector)
__global__ void k_edge2(const int4* __restrict__ row4,
                        const int4* __restrict__ col4,
                        float* __restrict__ out) {
    int i = blockIdx.x * blockDim.x + threadIdx.x;
    if (i < N_EDGES / 4) {
        int4 r = row4[i];
        int4 c = col4[i];
        atomicAdd(&out[c.x], g_t[r.x]);
        atomicAdd(&out[c.y], g_t[r.y]);
        atomicAdd(&out[c.z], g_t[r.z]);
        atomicAdd(&out[c.w], g_t[r.w]);
    }
}

// K6: out = relu(dis[n]*out_raw + b2)
__global__ void k_final(float* __restrict__ out, const float* __restrict__ b2) {
    int n = blockIdx.x * blockDim.x + threadIdx.x;
    if (n < N_NODES) {
        out[n] = fmaxf(fmaf(g_dis[n], out[n], b2[0]), 0.0f);
    }
}

// ---------------------------------------------------------------------------
extern "C" void kernel_launch(void* const* d_in, const int* in_sizes, int n_in,
                              void* d_out, int out_size) {
    const float* x  = (const float*)d_in[0];   // [N,2] f32
    const int*   ei = (const int*)d_in[1];     // [2,E] int32 (JAX x64 off)
    const float* W1 = (const float*)d_in[2];   // [2,64]
    const float* b1 = (const float*)d_in[3];   // [64]
    const float* W2 = (const float*)d_in[4];   // [64,1]
    const float* b2 = (const float*)d_in[5];   // [1]
    float*       out = (float*)d_out;          // [N,1]

    const int4* row4 = (const int4*)ei;               // source
    const int4* col4 = (const int4*)(ei + N_EDGES);   // target

    const int BT = 256;
    const int nodeBlocks  = (N_NODES + BT - 1) / BT;
    const int edgeBlocks4 = (N_EDGES / 4 + BT - 1) / BT;

    k_zero   <<<nodeBlocks, BT>>>(out);
    k_deg    <<<edgeBlocks4, BT>>>(col4);
    k_dis    <<<nodeBlocks, BT>>>(x);
    k_edge1  <<<edgeBlocks4, BT>>>(row4, col4);
    k_nodemid<<<nodeBlocks, BT>>>(W1, b1, W2);
    k_edge2  <<<edgeBlocks4, BT>>>(row4, col4, out);
    k_final  <<<nodeBlocks, BT>>>(out, b2);
}